// round 1
// baseline (speedup 1.0000x reference)
#include <cuda_runtime.h>

#define NUM_DRUG 50000
#define NUM_CELL 20000
#define HDIM     128
#define NEDGE    600000
#define NBATCH   4096

// ---------------- scratch (device globals; no runtime allocation) ----------
__device__ __align__(16) float g_h_drug[NUM_DRUG * HDIM];
__device__ __align__(16) float g_h_cell[NUM_CELL * HDIM];
__device__ __align__(16) float g_acc_drug[NUM_DRUG * HDIM];
__device__ __align__(16) float g_acc_cell[NUM_CELL * HDIM];
__device__ float g_cnt_drug[NUM_DRUG];
__device__ float g_cnt_cell[NUM_CELL];

// ---------------- scatter-add: one warp per edge ---------------------------
// acc[dst] += h[src]  (128 floats as 32 x float4), optionally cnt[dst] += 1
__global__ void scatter_kernel(const float* __restrict__ h,
                               const int* __restrict__ src,
                               const int* __restrict__ dst,
                               float* __restrict__ acc,
                               float* __restrict__ cnt,
                               int ne, int add_cnt)
{
    int warp = (blockIdx.x * blockDim.x + threadIdx.x) >> 5;
    int lane = threadIdx.x & 31;
    if (warp >= ne) return;
    int s = src[warp];
    int d = dst[warp];
    float4 v = reinterpret_cast<const float4*>(h)[s * 32 + lane];
    // 128-bit vector reduction (sm_90+)
    atomicAdd(reinterpret_cast<float4*>(acc) + d * 32 + lane, v);
    if (add_cnt && lane == 0) atomicAdd(cnt + d, 1.0f);
}

// ---------------- fused: mean -> GEMM (x @ W^T) -> residual -> LN -> ReLU --
// One 128-thread block processes 4 rows per iteration. W^T held in smem.
// smem layout: WT[128*128] | xT[128*4] | red[8]
#define FUSED_SMEM ((HDIM * HDIM + HDIM * 4 + 8) * sizeof(float))

__global__ void fused_update_kernel(const float* __restrict__ acc,
                                    const float* __restrict__ cnt,
                                    const float* __restrict__ hold,
                                    float* __restrict__ hnew,
                                    const float* __restrict__ W,   // [H,H] row-major W[out][k]
                                    const float* __restrict__ gam,
                                    const float* __restrict__ bet,
                                    int nrows)
{
    extern __shared__ float sm[];
    float* WT  = sm;                       // WT[k*128 + t] = W[t*128 + k]
    float* xT  = sm + HDIM * HDIM;         // xT[k*4 + r]
    float* red = xT + HDIM * 4;

    const int t = threadIdx.x;             // 0..127
    const int warp = t >> 5, lane = t & 31;

    // load W transposed into smem (once per block)
    for (int i = t; i < HDIM * HDIM; i += 128) {
        int out = i & (HDIM - 1);
        int k   = i >> 7;
        WT[i] = W[out * HDIM + k];
    }
    const float gg = gam[t];
    const float bb = bet[t];
    __syncthreads();

    const int ngroups = nrows >> 2;        // nrows divisible by 4 here
    for (int gi = blockIdx.x; gi < ngroups; gi += gridDim.x) {
        const int row0 = gi * 4;

        // load 4 rows transposed: xT[k][r] = acc[row0+r][k] / max(cnt,1)
        float4 xv;
        {
            float c0 = cnt[row0 + 0]; c0 = c0 < 1.f ? 1.f : c0;
            float c1 = cnt[row0 + 1]; c1 = c1 < 1.f ? 1.f : c1;
            float c2 = cnt[row0 + 2]; c2 = c2 < 1.f ? 1.f : c2;
            float c3 = cnt[row0 + 3]; c3 = c3 < 1.f ? 1.f : c3;
            xv.x = acc[(row0 + 0) * HDIM + t] / c0;
            xv.y = acc[(row0 + 1) * HDIM + t] / c1;
            xv.z = acc[(row0 + 2) * HDIM + t] / c2;
            xv.w = acc[(row0 + 3) * HDIM + t] / c3;
            reinterpret_cast<float4*>(xT)[t] = xv;   // xT[t*4 .. t*4+3]
        }
        __syncthreads();

        // y[r][t] = sum_k x[r][k] * W[t][k]
        float y0 = 0.f, y1 = 0.f, y2 = 0.f, y3 = 0.f;
        #pragma unroll
        for (int k = 0; k < HDIM; k++) {
            float w = WT[k * HDIM + t];
            float4 x4 = reinterpret_cast<const float4*>(xT)[k];  // broadcast
            y0 = fmaf(w, x4.x, y0);
            y1 = fmaf(w, x4.y, y1);
            y2 = fmaf(w, x4.z, y2);
            y3 = fmaf(w, x4.w, y3);
        }

        // residual + LayerNorm + ReLU per row
        #pragma unroll
        for (int r = 0; r < 4; r++) {
            float y = (r == 0) ? y0 : (r == 1) ? y1 : (r == 2) ? y2 : y3;
            y += hold[(row0 + r) * HDIM + t];

            float s = y, s2 = y * y;
            #pragma unroll
            for (int o = 16; o; o >>= 1) {
                s  += __shfl_xor_sync(0xffffffffu, s,  o);
                s2 += __shfl_xor_sync(0xffffffffu, s2, o);
            }
            if (lane == 0) { red[warp] = s; red[4 + warp] = s2; }
            __syncthreads();
            s  = red[0] + red[1] + red[2] + red[3];
            s2 = red[4] + red[5] + red[6] + red[7];
            __syncthreads();

            float mu  = s * (1.0f / HDIM);
            float var = s2 * (1.0f / HDIM) - mu * mu;
            float o   = (y - mu) * rsqrtf(var + 1e-5f) * gg + bb;
            hnew[(row0 + r) * HDIM + t] = o > 0.f ? o : 0.f;
        }
        __syncthreads();   // xT reused next group
    }
}

// ---------------- final: logit = [h_d | h_c] . wf + b ; sigmoid ------------
__global__ void final_kernel(const float* __restrict__ hd,
                             const float* __restrict__ hc,
                             const int* __restrict__ did,
                             const int* __restrict__ cid,
                             const float* __restrict__ wf,   // [256]
                             const float* __restrict__ bf,   // [1]
                             float* __restrict__ out, int nb)
{
    int warp = (blockIdx.x * blockDim.x + threadIdx.x) >> 5;
    int lane = threadIdx.x & 31;
    if (warp >= nb) return;
    int d = did[warp], c = cid[warp];
    float4 a  = reinterpret_cast<const float4*>(hd)[d * 32 + lane];
    float4 w1 = reinterpret_cast<const float4*>(wf)[lane];
    float4 b4 = reinterpret_cast<const float4*>(hc)[c * 32 + lane];
    float4 w2 = reinterpret_cast<const float4*>(wf)[32 + lane];
    float s = a.x * w1.x + a.y * w1.y + a.z * w1.z + a.w * w1.w
            + b4.x * w2.x + b4.y * w2.y + b4.z * w2.z + b4.w * w2.w;
    #pragma unroll
    for (int o = 16; o; o >>= 1) s += __shfl_xor_sync(0xffffffffu, s, o);
    if (lane == 0) {
        float x = s + bf[0];
        out[warp] = 1.0f / (1.0f + expf(-x));
    }
}

// ---------------------------------------------------------------------------
extern "C" void kernel_launch(void* const* d_in, const int* in_sizes, int n_in,
                              void* d_out, int out_size)
{
    const float* emb_drug  = (const float*)d_in[0];
    const float* emb_cell  = (const float*)d_in[1];
    const float* W_dt      = (const float*)d_in[2];
    const float* W_td      = (const float*)d_in[3];
    const float* ln_drug_g = (const float*)d_in[4];
    const float* ln_drug_b = (const float*)d_in[5];
    const float* ln_cell_g = (const float*)d_in[6];
    const float* ln_cell_b = (const float*)d_in[7];
    const float* W_final_w = (const float*)d_in[8];
    const float* W_final_b = (const float*)d_in[9];
    const int* edge_dt_src = (const int*)d_in[10];
    const int* edge_dt_dst = (const int*)d_in[11];
    const int* edge_td_src = (const int*)d_in[12];
    const int* edge_td_dst = (const int*)d_in[13];
    const int* drug_ids    = (const int*)d_in[14];
    const int* cell_ids    = (const int*)d_in[15];
    float* out = (float*)d_out;

    float *h_drug, *h_cell, *acc_drug, *acc_cell, *cnt_drug, *cnt_cell;
    cudaGetSymbolAddress((void**)&h_drug,  g_h_drug);
    cudaGetSymbolAddress((void**)&h_cell,  g_h_cell);
    cudaGetSymbolAddress((void**)&acc_drug, g_acc_drug);
    cudaGetSymbolAddress((void**)&acc_cell, g_acc_cell);
    cudaGetSymbolAddress((void**)&cnt_drug, g_cnt_drug);
    cudaGetSymbolAddress((void**)&cnt_cell, g_cnt_cell);

    cudaFuncSetAttribute(fused_update_kernel,
                         cudaFuncAttributeMaxDynamicSharedMemorySize,
                         (int)FUSED_SMEM);

    const int scatter_blocks = (NEDGE * 32) / 256;   // exact: 75000
    const int fused_blocks   = 444;                  // ~3 CTAs/SM x 148 SMs
    const int final_blocks   = (NBATCH * 32) / 256;  // exact: 512

    // counts are identical across layers: compute once
    cudaMemsetAsync(cnt_drug, 0, NUM_DRUG * sizeof(float));
    cudaMemsetAsync(cnt_cell, 0, NUM_CELL * sizeof(float));

    // ---------------- layer 0 (reads emb_*) ----------------
    cudaMemsetAsync(acc_drug, 0, (size_t)NUM_DRUG * HDIM * sizeof(float));
    cudaMemsetAsync(acc_cell, 0, (size_t)NUM_CELL * HDIM * sizeof(float));

    scatter_kernel<<<scatter_blocks, 256>>>(emb_drug, edge_dt_src, edge_dt_dst,
                                            acc_cell, cnt_cell, NEDGE, 1);
    scatter_kernel<<<scatter_blocks, 256>>>(emb_cell, edge_td_src, edge_td_dst,
                                            acc_drug, cnt_drug, NEDGE, 1);

    fused_update_kernel<<<fused_blocks, 128, FUSED_SMEM>>>(
        acc_drug, cnt_drug, emb_drug, h_drug, W_td, ln_drug_g, ln_drug_b, NUM_DRUG);
    fused_update_kernel<<<fused_blocks, 128, FUSED_SMEM>>>(
        acc_cell, cnt_cell, emb_cell, h_cell, W_dt, ln_cell_g, ln_cell_b, NUM_CELL);

    // ---------------- layer 1 (reads g_h_*) ----------------
    cudaMemsetAsync(acc_drug, 0, (size_t)NUM_DRUG * HDIM * sizeof(float));
    cudaMemsetAsync(acc_cell, 0, (size_t)NUM_CELL * HDIM * sizeof(float));

    scatter_kernel<<<scatter_blocks, 256>>>(h_drug, edge_dt_src, edge_dt_dst,
                                            acc_cell, cnt_cell, NEDGE, 0);
    scatter_kernel<<<scatter_blocks, 256>>>(h_cell, edge_td_src, edge_td_dst,
                                            acc_drug, cnt_drug, NEDGE, 0);

    fused_update_kernel<<<fused_blocks, 128, FUSED_SMEM>>>(
        acc_drug, cnt_drug, h_drug, h_drug, W_td, ln_drug_g, ln_drug_b, NUM_DRUG);
    fused_update_kernel<<<fused_blocks, 128, FUSED_SMEM>>>(
        acc_cell, cnt_cell, h_cell, h_cell, W_dt, ln_cell_g, ln_cell_b, NUM_CELL);

    // ---------------- final head ----------------
    final_kernel<<<final_blocks, 256>>>(h_drug, h_cell, drug_ids, cell_ids,
                                        W_final_w, W_final_b, out, NBATCH);
}

// round 2
// speedup vs baseline: 1.9975x; 1.9975x over previous
#include <cuda_runtime.h>

#define NUM_DRUG 50000
#define NUM_CELL 20000
#define HDIM     128
#define NEDGE    600000
#define NBATCH   4096

// ---------------- scratch (device globals; no runtime allocation) ----------
__device__ __align__(16) float g_h_drug[NUM_DRUG * HDIM];
__device__ __align__(16) float g_h_cell[NUM_CELL * HDIM];
__device__ __align__(16) float g_acc_drug[NUM_DRUG * HDIM];
__device__ __align__(16) float g_acc_cell[NUM_CELL * HDIM];
__device__ __align__(16) float g_WT_td[HDIM * HDIM];   // W_td transposed [k][out]
__device__ __align__(16) float g_WT_dt[HDIM * HDIM];   // W_dt transposed [k][out]
__device__ int g_off_drug[NUM_DRUG + 1];
__device__ int g_off_cell[NUM_CELL + 1];
__device__ int g_cur_drug[NUM_DRUG];
__device__ int g_cur_cell[NUM_CELL];
__device__ int g_csr_td[NEDGE];   // per drug-dst: source cell ids
__device__ int g_csr_dt[NEDGE];   // per cell-dst: source drug ids

// ---------------- f32x2 helpers -------------------------------------------
__device__ __forceinline__ unsigned long long splat2(float x) {
    unsigned long long r; unsigned xi = __float_as_uint(x);
    asm("mov.b64 %0, {%1, %1};" : "=l"(r) : "r"(xi));
    return r;
}
__device__ __forceinline__ unsigned long long fma2(unsigned long long a,
                                                   unsigned long long b,
                                                   unsigned long long c) {
    unsigned long long d;
    asm("fma.rn.f32x2 %0, %1, %2, %3;" : "=l"(d) : "l"(a), "l"(b), "l"(c));
    return d;
}
__device__ __forceinline__ float lo2(unsigned long long v) {
    return __uint_as_float((unsigned)(v & 0xffffffffull));
}
__device__ __forceinline__ float hi2(unsigned long long v) {
    return __uint_as_float((unsigned)(v >> 32));
}

// ---------------- CSR build ------------------------------------------------
__global__ void hist_kernel(const int* __restrict__ dst, int* __restrict__ cnt, int ne) {
    int i = blockIdx.x * blockDim.x + threadIdx.x;
    if (i < ne) atomicAdd(&cnt[dst[i]], 1);
}

// single-block exclusive scan: off[0]=0, off[i+1]=sum(cnt[0..i])
__global__ void scan_kernel(const int* __restrict__ cnt, int* __restrict__ off, int n) {
    __shared__ int ws[32];
    __shared__ int carry;
    int t = threadIdx.x, lane = t & 31, w = t >> 5;
    if (t == 0) carry = 0;
    __syncthreads();
    for (int base = 0; base < n; base += 1024) {
        int i = base + t;
        int x = (i < n) ? cnt[i] : 0;
        #pragma unroll
        for (int o = 1; o < 32; o <<= 1) {
            int y = __shfl_up_sync(0xffffffffu, x, o);
            if (lane >= o) x += y;
        }
        if (lane == 31) ws[w] = x;
        __syncthreads();
        if (w == 0) {
            int s = ws[lane];
            #pragma unroll
            for (int o = 1; o < 32; o <<= 1) {
                int y = __shfl_up_sync(0xffffffffu, s, o);
                if (lane >= o) s += y;
            }
            ws[lane] = s;
        }
        __syncthreads();
        int incl = x + (w ? ws[w - 1] : 0) + carry;
        if (i < n) off[i + 1] = incl;
        __syncthreads();
        if (t == 1023) carry = incl;
        __syncthreads();
    }
    if (threadIdx.x == 0) off[0] = 0;
}

__global__ void fill_kernel(const int* __restrict__ src, const int* __restrict__ dst,
                            const int* __restrict__ off, int* __restrict__ cur,
                            int* __restrict__ csr, int ne) {
    int i = blockIdx.x * blockDim.x + threadIdx.x;
    if (i < ne) {
        int d = dst[i];
        int p = off[d] + atomicAdd(&cur[d], 1);
        csr[p] = src[i];
    }
}

// ---------------- W transpose (once per launch) ---------------------------
__global__ void transpose_w_kernel(const float* __restrict__ W, float* __restrict__ WT) {
    int i = blockIdx.x * blockDim.x + threadIdx.x;   // 16384
    int k = i & 127, out = i >> 7;
    WT[k * HDIM + out] = W[out * HDIM + k];
}

// ---------------- gather-mean: one warp per dst row ------------------------
__device__ __forceinline__ void add4(float4& a, const float4 b) {
    a.x += b.x; a.y += b.y; a.z += b.z; a.w += b.w;
}

__global__ void gather_mean_kernel(const float* __restrict__ h,
                                   const int* __restrict__ off,
                                   const int* __restrict__ csr,
                                   float* __restrict__ acc, int nrows)
{
    int row  = (blockIdx.x * blockDim.x + threadIdx.x) >> 5;
    int lane = threadIdx.x & 31;
    if (row >= nrows) return;
    int b = off[row], e = off[row + 1];
    const float4* h4 = reinterpret_cast<const float4*>(h);
    float4 a0 = {0,0,0,0}, a1 = {0,0,0,0}, a2 = {0,0,0,0}, a3 = {0,0,0,0};
    int i = b;
    for (; i + 4 <= e; i += 4) {
        int s0 = csr[i], s1 = csr[i+1], s2 = csr[i+2], s3 = csr[i+3];
        add4(a0, h4[s0 * 32 + lane]);
        add4(a1, h4[s1 * 32 + lane]);
        add4(a2, h4[s2 * 32 + lane]);
        add4(a3, h4[s3 * 32 + lane]);
    }
    for (; i < e; i++) {
        int s = csr[i];
        add4(a0, h4[s * 32 + lane]);
    }
    add4(a0, a1); add4(a2, a3); add4(a0, a2);
    int deg = e - b;
    float inv = 1.0f / (float)(deg < 1 ? 1 : deg);
    a0.x *= inv; a0.y *= inv; a0.z *= inv; a0.w *= inv;
    reinterpret_cast<float4*>(acc)[row * 32 + lane] = a0;
}

// ---------------- fused: GEMM (x @ W^T) -> residual -> LN -> ReLU ----------
// block = 128 threads, 32 rows/group; warp w: rows 8w..8w+7; thread: cols 4*(t&31)..+3
#define GROUP_ROWS 32
#define FUSED_SMEM ((HDIM * HDIM + GROUP_ROWS * HDIM) * sizeof(float))   // 80 KB

__global__ void __launch_bounds__(128)
fused_update_kernel(const float* __restrict__ acc,     // mean-aggregated msgs
                    const float* __restrict__ hold,
                    float* __restrict__ hnew,
                    const float* __restrict__ WTg,     // pre-transposed [k][out]
                    const float* __restrict__ gam,
                    const float* __restrict__ bet,
                    int nrows)
{
    extern __shared__ float sm[];
    float* WT = sm;                         // [128][128]
    float* XS = sm + HDIM * HDIM;           // [32 rows][128 k]

    const int t    = threadIdx.x;
    const int lane = t & 31;
    const int w    = t >> 5;
    const int c0   = 4 * lane;

    // load pre-transposed W (coalesced float4 copy)
    {
        const float4* s4 = reinterpret_cast<const float4*>(WTg);
        float4* d4 = reinterpret_cast<float4*>(WT);
        #pragma unroll
        for (int i = t; i < HDIM * HDIM / 4; i += 128) d4[i] = s4[i];
    }
    const float4 g4 = reinterpret_cast<const float4*>(gam)[lane];
    const float4 b4 = reinterpret_cast<const float4*>(bet)[lane];
    __syncthreads();

    const int ngroups = (nrows + GROUP_ROWS - 1) / GROUP_ROWS;
    const float4 z4 = {0.f, 0.f, 0.f, 0.f};

    for (int gi = blockIdx.x; gi < ngroups; gi += gridDim.x) {
        const int row0 = gi * GROUP_ROWS;

        // load 32 rows of x into smem (row-major, conflict-free)
        __syncthreads();
        {
            const float4* a4 = reinterpret_cast<const float4*>(acc);
            float4* x4 = reinterpret_cast<float4*>(XS);
            #pragma unroll
            for (int i = t; i < GROUP_ROWS * 32; i += 128) {
                int r = i >> 5, q = i & 31;
                x4[r * 32 + q] = (row0 + r < nrows) ? a4[(row0 + r) * 32 + q] : z4;
            }
        }
        __syncthreads();

        // GEMM: acc2[i][p] = packed cols (c0+2p, c0+2p+1) for row 8w+i
        unsigned long long acc2[8][2];
        #pragma unroll
        for (int i = 0; i < 8; i++) { acc2[i][0] = 0ull; acc2[i][1] = 0ull; }

        for (int kt = 0; kt < HDIM; kt += 4) {
            float4 xv[8];
            #pragma unroll
            for (int i = 0; i < 8; i++)
                xv[i] = *reinterpret_cast<const float4*>(&XS[(8 * w + i) * HDIM + kt]);
            #pragma unroll
            for (int kk = 0; kk < 4; kk++) {
                ulonglong2 wv = *reinterpret_cast<const ulonglong2*>(
                    &WT[(kt + kk) * HDIM + c0]);
                #pragma unroll
                for (int i = 0; i < 8; i++) {
                    float xs = (kk == 0) ? xv[i].x : (kk == 1) ? xv[i].y
                             : (kk == 2) ? xv[i].z : xv[i].w;
                    unsigned long long s2 = splat2(xs);
                    acc2[i][0] = fma2(s2, wv.x, acc2[i][0]);
                    acc2[i][1] = fma2(s2, wv.y, acc2[i][1]);
                }
            }
        }

        // epilogue: residual + LayerNorm + ReLU, one row per warp at a time
        #pragma unroll
        for (int i = 0; i < 8; i++) {
            int grow = row0 + 8 * w + i;
            if (grow < nrows) {
                float4 hv = reinterpret_cast<const float4*>(hold)[grow * 32 + lane];
                float y0 = lo2(acc2[i][0]) + hv.x;
                float y1 = hi2(acc2[i][0]) + hv.y;
                float y2 = lo2(acc2[i][1]) + hv.z;
                float y3 = hi2(acc2[i][1]) + hv.w;

                float s = y0 + y1 + y2 + y3;
                float q = y0*y0 + y1*y1 + y2*y2 + y3*y3;
                #pragma unroll
                for (int o = 16; o; o >>= 1) {
                    s += __shfl_xor_sync(0xffffffffu, s, o);
                    q += __shfl_xor_sync(0xffffffffu, q, o);
                }
                float mu  = s * (1.0f / HDIM);
                float var = q * (1.0f / HDIM) - mu * mu;
                float rs  = rsqrtf(var + 1e-5f);
                float4 o4;
                o4.x = (y0 - mu) * rs * g4.x + b4.x; o4.x = o4.x > 0.f ? o4.x : 0.f;
                o4.y = (y1 - mu) * rs * g4.y + b4.y; o4.y = o4.y > 0.f ? o4.y : 0.f;
                o4.z = (y2 - mu) * rs * g4.z + b4.z; o4.z = o4.z > 0.f ? o4.z : 0.f;
                o4.w = (y3 - mu) * rs * g4.w + b4.w; o4.w = o4.w > 0.f ? o4.w : 0.f;
                reinterpret_cast<float4*>(hnew)[grow * 32 + lane] = o4;
            }
        }
    }
}

// ---------------- final head -----------------------------------------------
__global__ void final_kernel(const float* __restrict__ hd,
                             const float* __restrict__ hc,
                             const int* __restrict__ did,
                             const int* __restrict__ cid,
                             const float* __restrict__ wf,
                             const float* __restrict__ bf,
                             float* __restrict__ out, int nb)
{
    int warp = (blockIdx.x * blockDim.x + threadIdx.x) >> 5;
    int lane = threadIdx.x & 31;
    if (warp >= nb) return;
    int d = did[warp], c = cid[warp];
    float4 a  = reinterpret_cast<const float4*>(hd)[d * 32 + lane];
    float4 w1 = reinterpret_cast<const float4*>(wf)[lane];
    float4 b4 = reinterpret_cast<const float4*>(hc)[c * 32 + lane];
    float4 w2 = reinterpret_cast<const float4*>(wf)[32 + lane];
    float s = a.x * w1.x + a.y * w1.y + a.z * w1.z + a.w * w1.w
            + b4.x * w2.x + b4.y * w2.y + b4.z * w2.z + b4.w * w2.w;
    #pragma unroll
    for (int o = 16; o; o >>= 1) s += __shfl_xor_sync(0xffffffffu, s, o);
    if (lane == 0) {
        float x = s + bf[0];
        out[warp] = 1.0f / (1.0f + expf(-x));
    }
}

// ---------------------------------------------------------------------------
extern "C" void kernel_launch(void* const* d_in, const int* in_sizes, int n_in,
                              void* d_out, int out_size)
{
    const float* emb_drug  = (const float*)d_in[0];
    const float* emb_cell  = (const float*)d_in[1];
    const float* W_dt      = (const float*)d_in[2];
    const float* W_td      = (const float*)d_in[3];
    const float* ln_drug_g = (const float*)d_in[4];
    const float* ln_drug_b = (const float*)d_in[5];
    const float* ln_cell_g = (const float*)d_in[6];
    const float* ln_cell_b = (const float*)d_in[7];
    const float* W_final_w = (const float*)d_in[8];
    const float* W_final_b = (const float*)d_in[9];
    const int* edge_dt_src = (const int*)d_in[10];
    const int* edge_dt_dst = (const int*)d_in[11];
    const int* edge_td_src = (const int*)d_in[12];
    const int* edge_td_dst = (const int*)d_in[13];
    const int* drug_ids    = (const int*)d_in[14];
    const int* cell_ids    = (const int*)d_in[15];
    float* out = (float*)d_out;

    float *h_drug, *h_cell, *acc_drug, *acc_cell, *WT_td, *WT_dt;
    int *off_drug, *off_cell, *cur_drug, *cur_cell, *csr_td, *csr_dt;
    cudaGetSymbolAddress((void**)&h_drug,   g_h_drug);
    cudaGetSymbolAddress((void**)&h_cell,   g_h_cell);
    cudaGetSymbolAddress((void**)&acc_drug, g_acc_drug);
    cudaGetSymbolAddress((void**)&acc_cell, g_acc_cell);
    cudaGetSymbolAddress((void**)&WT_td,    g_WT_td);
    cudaGetSymbolAddress((void**)&WT_dt,    g_WT_dt);
    cudaGetSymbolAddress((void**)&off_drug, g_off_drug);
    cudaGetSymbolAddress((void**)&off_cell, g_off_cell);
    cudaGetSymbolAddress((void**)&cur_drug, g_cur_drug);
    cudaGetSymbolAddress((void**)&cur_cell, g_cur_cell);
    cudaGetSymbolAddress((void**)&csr_td,   g_csr_td);
    cudaGetSymbolAddress((void**)&csr_dt,   g_csr_dt);

    cudaFuncSetAttribute(fused_update_kernel,
                         cudaFuncAttributeMaxDynamicSharedMemorySize,
                         (int)FUSED_SMEM);

    const int eb = (NEDGE + 255) / 256;

    // ---------------- CSR build (edges identical across layers) ----------------
    cudaMemsetAsync(cur_drug, 0, NUM_DRUG * sizeof(int));
    cudaMemsetAsync(cur_cell, 0, NUM_CELL * sizeof(int));
    hist_kernel<<<eb, 256>>>(edge_td_dst, cur_drug, NEDGE);   // drug in-degree
    hist_kernel<<<eb, 256>>>(edge_dt_dst, cur_cell, NEDGE);   // cell in-degree
    scan_kernel<<<1, 1024>>>(cur_drug, off_drug, NUM_DRUG);
    scan_kernel<<<1, 1024>>>(cur_cell, off_cell, NUM_CELL);
    cudaMemsetAsync(cur_drug, 0, NUM_DRUG * sizeof(int));
    cudaMemsetAsync(cur_cell, 0, NUM_CELL * sizeof(int));
    fill_kernel<<<eb, 256>>>(edge_td_src, edge_td_dst, off_drug, cur_drug, csr_td, NEDGE);
    fill_kernel<<<eb, 256>>>(edge_dt_src, edge_dt_dst, off_cell, cur_cell, csr_dt, NEDGE);

    // pre-transpose weights
    transpose_w_kernel<<<HDIM * HDIM / 256, 256>>>(W_td, WT_td);
    transpose_w_kernel<<<HDIM * HDIM / 256, 256>>>(W_dt, WT_dt);

    const int gb_drug = (NUM_DRUG * 32 + 255) / 256;
    const int gb_cell = (NUM_CELL * 32 + 255) / 256;
    const int fused_blocks = 296;   // 2 CTAs/SM x 148 SMs
    const int final_blocks = (NBATCH * 32) / 256;

    // ---------------- layer 0 (reads emb_*) ----------------
    gather_mean_kernel<<<gb_drug, 256>>>(emb_cell, off_drug, csr_td, acc_drug, NUM_DRUG);
    gather_mean_kernel<<<gb_cell, 256>>>(emb_drug, off_cell, csr_dt, acc_cell, NUM_CELL);
    fused_update_kernel<<<fused_blocks, 128, FUSED_SMEM>>>(
        acc_drug, emb_drug, h_drug, WT_td, ln_drug_g, ln_drug_b, NUM_DRUG);
    fused_update_kernel<<<fused_blocks, 128, FUSED_SMEM>>>(
        acc_cell, emb_cell, h_cell, WT_dt, ln_cell_g, ln_cell_b, NUM_CELL);

    // ---------------- layer 1 (reads g_h_*) ----------------
    gather_mean_kernel<<<gb_drug, 256>>>(h_cell, off_drug, csr_td, acc_drug, NUM_DRUG);
    gather_mean_kernel<<<gb_cell, 256>>>(h_drug, off_cell, csr_dt, acc_cell, NUM_CELL);
    fused_update_kernel<<<fused_blocks, 128, FUSED_SMEM>>>(
        acc_drug, h_drug, h_drug, WT_td, ln_drug_g, ln_drug_b, NUM_DRUG);
    fused_update_kernel<<<fused_blocks, 128, FUSED_SMEM>>>(
        acc_cell, h_cell, h_cell, WT_dt, ln_cell_g, ln_cell_b, NUM_CELL);

    // ---------------- final head ----------------
    final_kernel<<<final_blocks, 256>>>(h_drug, h_cell, drug_ids, cell_ids,
                                        W_final_w, W_final_b, out, NBATCH);
}

// round 3
// speedup vs baseline: 2.5376x; 1.2704x over previous
#include <cuda_runtime.h>

#define NUM_DRUG 50000
#define NUM_CELL 20000
#define HDIM     128
#define NEDGE    600000
#define NBATCH   4096

#define G8_DRUG (NUM_DRUG / 8)   // 6250 warp-groups (divides exactly)
#define G8_CELL (NUM_CELL / 8)   // 2500

#define LAYER_BLOCKS 296
#define ND_BLOCKS    172         // blocks assigned to the drug side
#define WARPS        8           // 256 threads / block
#define LAYER_SMEM ((HDIM * HDIM + WARPS * 8 * HDIM) * sizeof(float))  // 96 KB

// ---------------- scratch (device globals; no runtime allocation) ----------
__device__ __align__(16) float g_hA_drug[NUM_DRUG * HDIM];
__device__ __align__(16) float g_hA_cell[NUM_CELL * HDIM];
__device__ __align__(16) float g_hB_drug[NUM_DRUG * HDIM];
__device__ __align__(16) float g_hB_cell[NUM_CELL * HDIM];
__device__ __align__(16) float g_WT_td[HDIM * HDIM];
__device__ __align__(16) float g_WT_dt[HDIM * HDIM];
__device__ int g_off_drug[NUM_DRUG + 1];
__device__ int g_off_cell[NUM_CELL + 1];
__device__ int g_cur_drug[NUM_DRUG];
__device__ int g_cur_cell[NUM_CELL];
__device__ int g_csr_td[NEDGE];   // per drug-dst: source cell ids
__device__ int g_csr_dt[NEDGE];   // per cell-dst: source drug ids

// ---------------- f32x2 helpers --------------------------------------------
__device__ __forceinline__ unsigned long long splat2(float x) {
    unsigned long long r; unsigned xi = __float_as_uint(x);
    asm("mov.b64 %0, {%1, %1};" : "=l"(r) : "r"(xi));
    return r;
}
__device__ __forceinline__ unsigned long long fma2(unsigned long long a,
                                                   unsigned long long b,
                                                   unsigned long long c) {
    unsigned long long d;
    asm("fma.rn.f32x2 %0, %1, %2, %3;" : "=l"(d) : "l"(a), "l"(b), "l"(c));
    return d;
}
__device__ __forceinline__ float lo2(unsigned long long v) {
    return __uint_as_float((unsigned)(v & 0xffffffffull));
}
__device__ __forceinline__ float hi2(unsigned long long v) {
    return __uint_as_float((unsigned)(v >> 32));
}

// ---------------- CSR build (both relations in single launches) ------------
__global__ void hist2_kernel(const int* __restrict__ dstA, int* __restrict__ cntA,
                             const int* __restrict__ dstB, int* __restrict__ cntB)
{
    int i = blockIdx.x * blockDim.x + threadIdx.x;
    if (i < NEDGE)               atomicAdd(&cntA[dstA[i]], 1);
    else if (i < 2 * NEDGE)      atomicAdd(&cntB[dstB[i - NEDGE]], 1);
}

// coarsened scan: 8 items/thread, block 0 = drug, block 1 = cell
__global__ void scan2_kernel(const int* __restrict__ cntA, int* __restrict__ offA,
                             const int* __restrict__ cntB, int* __restrict__ offB)
{
    const int* cnt = blockIdx.x == 0 ? cntA : cntB;
    int* off       = blockIdx.x == 0 ? offA : offB;
    const int n    = blockIdx.x == 0 ? NUM_DRUG : NUM_CELL;

    __shared__ int ws[32];
    __shared__ int s_carry;
    int t = threadIdx.x, lane = t & 31, w = t >> 5;
    if (t == 0) s_carry = 0;
    __syncthreads();

    for (int base = 0; base < n; base += 1024 * 8) {
        int idx = base + t * 8;
        int v[8];
        #pragma unroll
        for (int j = 0; j < 8; j++)
            v[j] = (idx + j < n) ? cnt[idx + j] : 0;
        #pragma unroll
        for (int j = 1; j < 8; j++) v[j] += v[j - 1];
        int tot = v[7];
        int x = tot;
        #pragma unroll
        for (int o = 1; o < 32; o <<= 1) {
            int y = __shfl_up_sync(0xffffffffu, x, o);
            if (lane >= o) x += y;
        }
        if (lane == 31) ws[w] = x;
        __syncthreads();
        if (w == 0) {
            int s = ws[lane];
            #pragma unroll
            for (int o = 1; o < 32; o <<= 1) {
                int y = __shfl_up_sync(0xffffffffu, s, o);
                if (lane >= o) s += y;
            }
            ws[lane] = s;
        }
        __syncthreads();
        int prefix = (x - tot) + (w ? ws[w - 1] : 0) + s_carry;
        #pragma unroll
        for (int j = 0; j < 8; j++)
            if (idx + j < n) off[idx + j + 1] = prefix + v[j];
        __syncthreads();
        if (t == 0) s_carry += ws[31];
        __syncthreads();
    }
    if (t == 0) off[0] = 0;
}

__global__ void fill2_kernel(const int* __restrict__ srcA, const int* __restrict__ dstA,
                             const int* __restrict__ offA, int* __restrict__ curA,
                             int* __restrict__ csrA,
                             const int* __restrict__ srcB, const int* __restrict__ dstB,
                             const int* __restrict__ offB, int* __restrict__ curB,
                             int* __restrict__ csrB)
{
    int i = blockIdx.x * blockDim.x + threadIdx.x;
    if (i < NEDGE) {
        int d = dstA[i];
        csrA[offA[d] + atomicAdd(&curA[d], 1)] = srcA[i];
    } else if (i < 2 * NEDGE) {
        int j = i - NEDGE;
        int d = dstB[j];
        csrB[offB[d] + atomicAdd(&curB[d], 1)] = srcB[j];
    }
}

__global__ void transpose2_kernel(const float* __restrict__ Wa, float* __restrict__ WTa,
                                  const float* __restrict__ Wb, float* __restrict__ WTb)
{
    int i = blockIdx.x * blockDim.x + threadIdx.x;
    int j = i & (HDIM * HDIM - 1);
    int k = j & 127, out = j >> 7;
    if (i < HDIM * HDIM) WTa[k * HDIM + out] = Wa[out * HDIM + k];
    else                 WTb[k * HDIM + out] = Wb[out * HDIM + k];
}

// ---------------- layer: gather-mean -> GEMM -> residual -> LN -> ReLU -----
// Each warp owns 8 rows: gathers them into its private XS slab, then GEMM +
// epilogue. No block syncs in the main loop.
__global__ void __launch_bounds__(256, 2)
layer_kernel(const float* __restrict__ hd_in, const float* __restrict__ hc_in,
             float* __restrict__ hd_out, float* __restrict__ hc_out,
             const float* __restrict__ WT_td, const float* __restrict__ WT_dt,
             const float* __restrict__ gd, const float* __restrict__ bd,
             const float* __restrict__ gc, const float* __restrict__ bc,
             const int* __restrict__ off_d, const int* __restrict__ csr_d,
             const int* __restrict__ off_c, const int* __restrict__ csr_c)
{
    const bool isD = blockIdx.x < ND_BLOCKS;
    const float* src  = isD ? hc_in : hd_in;   // gather messages from other side
    const float* hold = isD ? hd_in : hc_in;
    float* outp       = isD ? hd_out : hc_out;
    const float* WTg  = isD ? WT_td : WT_dt;
    const float* gam  = isD ? gd : gc;
    const float* bet  = isD ? bd : bc;
    const int* off    = isD ? off_d : off_c;
    const int* csr    = isD ? csr_d : csr_c;
    const int ng8     = isD ? G8_DRUG : G8_CELL;
    const int nb      = isD ? ND_BLOCKS : (LAYER_BLOCKS - ND_BLOCKS);
    const int bid     = isD ? blockIdx.x : blockIdx.x - ND_BLOCKS;

    extern __shared__ float sm[];
    float* WT = sm;                                  // [128][128]
    const int t = threadIdx.x, lane = t & 31, w = t >> 5;
    float* XS = sm + HDIM * HDIM + w * (8 * HDIM);   // warp-private [8][128]
    const int c0 = 4 * lane;

    // load pre-transposed W (coalesced float4 copy)
    {
        const float4* s4 = reinterpret_cast<const float4*>(WTg);
        float4* d4 = reinterpret_cast<float4*>(WT);
        #pragma unroll
        for (int i = t; i < HDIM * HDIM / 4; i += 256) d4[i] = s4[i];
    }
    const float4 g4 = reinterpret_cast<const float4*>(gam)[lane];
    const float4 b4 = reinterpret_cast<const float4*>(bet)[lane];
    __syncthreads();

    const float4* src4  = reinterpret_cast<const float4*>(src);
    const float4* hold4 = reinterpret_cast<const float4*>(hold);
    float4* out4        = reinterpret_cast<float4*>(outp);

    for (int wg = bid * WARPS + w; wg < ng8; wg += nb * WARPS) {
        const int row0 = wg * 8;

        // ---- gather-mean 8 rows into XS ----
        #pragma unroll
        for (int i = 0; i < 8; i++) {
            int r = row0 + i;
            int jb = off[r], je = off[r + 1];
            float4 a0 = {0,0,0,0}, a1 = {0,0,0,0}, a2 = {0,0,0,0}, a3 = {0,0,0,0};
            int j = jb;
            for (; j + 4 <= je; j += 4) {
                int s0 = csr[j], s1 = csr[j+1], s2 = csr[j+2], s3 = csr[j+3];
                float4 v0 = src4[s0 * 32 + lane];
                float4 v1 = src4[s1 * 32 + lane];
                float4 v2 = src4[s2 * 32 + lane];
                float4 v3 = src4[s3 * 32 + lane];
                a0.x += v0.x; a0.y += v0.y; a0.z += v0.z; a0.w += v0.w;
                a1.x += v1.x; a1.y += v1.y; a1.z += v1.z; a1.w += v1.w;
                a2.x += v2.x; a2.y += v2.y; a2.z += v2.z; a2.w += v2.w;
                a3.x += v3.x; a3.y += v3.y; a3.z += v3.z; a3.w += v3.w;
            }
            for (; j < je; j++) {
                float4 v = src4[csr[j] * 32 + lane];
                a0.x += v.x; a0.y += v.y; a0.z += v.z; a0.w += v.w;
            }
            a0.x += a1.x + a2.x + a3.x;
            a0.y += a1.y + a2.y + a3.y;
            a0.z += a1.z + a2.z + a3.z;
            a0.w += a1.w + a2.w + a3.w;
            int deg = je - jb;
            float inv = 1.0f / (float)(deg < 1 ? 1 : deg);
            a0.x *= inv; a0.y *= inv; a0.z *= inv; a0.w *= inv;
            *reinterpret_cast<float4*>(&XS[i * HDIM + c0]) = a0;
        }
        __syncwarp();

        // ---- GEMM: y[i][out] = sum_k x[i][k] * W[out][k], f32x2 packed ----
        unsigned long long acc2[8][2];
        #pragma unroll
        for (int i = 0; i < 8; i++) { acc2[i][0] = 0ull; acc2[i][1] = 0ull; }

        for (int kt = 0; kt < HDIM; kt += 4) {
            float4 xv[8];
            #pragma unroll
            for (int i = 0; i < 8; i++)
                xv[i] = *reinterpret_cast<const float4*>(&XS[i * HDIM + kt]);
            #pragma unroll
            for (int kk = 0; kk < 4; kk++) {
                ulonglong2 wv = *reinterpret_cast<const ulonglong2*>(
                    &WT[(kt + kk) * HDIM + c0]);
                #pragma unroll
                for (int i = 0; i < 8; i++) {
                    float xs = (kk == 0) ? xv[i].x : (kk == 1) ? xv[i].y
                             : (kk == 2) ? xv[i].z : xv[i].w;
                    unsigned long long s2 = splat2(xs);
                    acc2[i][0] = fma2(s2, wv.x, acc2[i][0]);
                    acc2[i][1] = fma2(s2, wv.y, acc2[i][1]);
                }
            }
        }

        // ---- epilogue: residual + LayerNorm + ReLU ----
        #pragma unroll
        for (int i = 0; i < 8; i++) {
            int grow = row0 + i;
            float4 hv = hold4[grow * 32 + lane];
            float y0 = lo2(acc2[i][0]) + hv.x;
            float y1 = hi2(acc2[i][0]) + hv.y;
            float y2 = lo2(acc2[i][1]) + hv.z;
            float y3 = hi2(acc2[i][1]) + hv.w;

            float s = y0 + y1 + y2 + y3;
            float q = y0*y0 + y1*y1 + y2*y2 + y3*y3;
            #pragma unroll
            for (int o = 16; o; o >>= 1) {
                s += __shfl_xor_sync(0xffffffffu, s, o);
                q += __shfl_xor_sync(0xffffffffu, q, o);
            }
            float mu  = s * (1.0f / HDIM);
            float var = q * (1.0f / HDIM) - mu * mu;
            float rs  = rsqrtf(var + 1e-5f);
            float4 o4;
            o4.x = (y0 - mu) * rs * g4.x + b4.x; o4.x = o4.x > 0.f ? o4.x : 0.f;
            o4.y = (y1 - mu) * rs * g4.y + b4.y; o4.y = o4.y > 0.f ? o4.y : 0.f;
            o4.z = (y2 - mu) * rs * g4.z + b4.z; o4.z = o4.z > 0.f ? o4.z : 0.f;
            o4.w = (y3 - mu) * rs * g4.w + b4.w; o4.w = o4.w > 0.f ? o4.w : 0.f;
            out4[grow * 32 + lane] = o4;
        }
        __syncwarp();   // XS reused next iteration
    }
}

// ---------------- final head -------------------------------------------------
__global__ void final_kernel(const float* __restrict__ hd,
                             const float* __restrict__ hc,
                             const int* __restrict__ did,
                             const int* __restrict__ cid,
                             const float* __restrict__ wf,
                             const float* __restrict__ bf,
                             float* __restrict__ out, int nb)
{
    int warp = (blockIdx.x * blockDim.x + threadIdx.x) >> 5;
    int lane = threadIdx.x & 31;
    if (warp >= nb) return;
    int d = did[warp], c = cid[warp];
    float4 a  = reinterpret_cast<const float4*>(hd)[d * 32 + lane];
    float4 w1 = reinterpret_cast<const float4*>(wf)[lane];
    float4 b4 = reinterpret_cast<const float4*>(hc)[c * 32 + lane];
    float4 w2 = reinterpret_cast<const float4*>(wf)[32 + lane];
    float s = a.x * w1.x + a.y * w1.y + a.z * w1.z + a.w * w1.w
            + b4.x * w2.x + b4.y * w2.y + b4.z * w2.z + b4.w * w2.w;
    #pragma unroll
    for (int o = 16; o; o >>= 1) s += __shfl_xor_sync(0xffffffffu, s, o);
    if (lane == 0) {
        float x = s + bf[0];
        out[warp] = 1.0f / (1.0f + expf(-x));
    }
}

// ---------------------------------------------------------------------------
extern "C" void kernel_launch(void* const* d_in, const int* in_sizes, int n_in,
                              void* d_out, int out_size)
{
    const float* emb_drug  = (const float*)d_in[0];
    const float* emb_cell  = (const float*)d_in[1];
    const float* W_dt      = (const float*)d_in[2];
    const float* W_td      = (const float*)d_in[3];
    const float* ln_drug_g = (const float*)d_in[4];
    const float* ln_drug_b = (const float*)d_in[5];
    const float* ln_cell_g = (const float*)d_in[6];
    const float* ln_cell_b = (const float*)d_in[7];
    const float* W_final_w = (const float*)d_in[8];
    const float* W_final_b = (const float*)d_in[9];
    const int* edge_dt_src = (const int*)d_in[10];
    const int* edge_dt_dst = (const int*)d_in[11];
    const int* edge_td_src = (const int*)d_in[12];
    const int* edge_td_dst = (const int*)d_in[13];
    const int* drug_ids    = (const int*)d_in[14];
    const int* cell_ids    = (const int*)d_in[15];
    float* out = (float*)d_out;

    float *hA_d, *hA_c, *hB_d, *hB_c, *WT_td, *WT_dt;
    int *off_d, *off_c, *cur_d, *cur_c, *csr_td, *csr_dt;
    cudaGetSymbolAddress((void**)&hA_d,   g_hA_drug);
    cudaGetSymbolAddress((void**)&hA_c,   g_hA_cell);
    cudaGetSymbolAddress((void**)&hB_d,   g_hB_drug);
    cudaGetSymbolAddress((void**)&hB_c,   g_hB_cell);
    cudaGetSymbolAddress((void**)&WT_td,  g_WT_td);
    cudaGetSymbolAddress((void**)&WT_dt,  g_WT_dt);
    cudaGetSymbolAddress((void**)&off_d,  g_off_drug);
    cudaGetSymbolAddress((void**)&off_c,  g_off_cell);
    cudaGetSymbolAddress((void**)&cur_d,  g_cur_drug);
    cudaGetSymbolAddress((void**)&cur_c,  g_cur_cell);
    cudaGetSymbolAddress((void**)&csr_td, g_csr_td);
    cudaGetSymbolAddress((void**)&csr_dt, g_csr_dt);

    cudaFuncSetAttribute(layer_kernel,
                         cudaFuncAttributeMaxDynamicSharedMemorySize,
                         (int)LAYER_SMEM);

    const int eb2 = (2 * NEDGE + 255) / 256;

    // ---------------- CSR build ----------------
    cudaMemsetAsync(cur_d, 0, NUM_DRUG * sizeof(int));
    cudaMemsetAsync(cur_c, 0, NUM_CELL * sizeof(int));
    hist2_kernel<<<eb2, 256>>>(edge_td_dst, cur_d, edge_dt_dst, cur_c);
    scan2_kernel<<<2, 1024>>>(cur_d, off_d, cur_c, off_c);
    cudaMemsetAsync(cur_d, 0, NUM_DRUG * sizeof(int));
    cudaMemsetAsync(cur_c, 0, NUM_CELL * sizeof(int));
    fill2_kernel<<<eb2, 256>>>(edge_td_src, edge_td_dst, off_d, cur_d, csr_td,
                               edge_dt_src, edge_dt_dst, off_c, cur_c, csr_dt);
    transpose2_kernel<<<2 * HDIM * HDIM / 256, 256>>>(W_td, WT_td, W_dt, WT_dt);

    // ---------------- layers ----------------
    layer_kernel<<<LAYER_BLOCKS, 256, LAYER_SMEM>>>(
        emb_drug, emb_cell, hA_d, hA_c, WT_td, WT_dt,
        ln_drug_g, ln_drug_b, ln_cell_g, ln_cell_b,
        off_d, csr_td, off_c, csr_dt);
    layer_kernel<<<LAYER_BLOCKS, 256, LAYER_SMEM>>>(
        hA_d, hA_c, hB_d, hB_c, WT_td, WT_dt,
        ln_drug_g, ln_drug_b, ln_cell_g, ln_cell_b,
        off_d, csr_td, off_c, csr_dt);

    // ---------------- final head ----------------
    final_kernel<<<(NBATCH * 32) / 256, 256>>>(hB_d, hB_c, drug_ids, cell_ids,
                                               W_final_w, W_final_b, out, NBATCH);
}